// round 7
// baseline (speedup 1.0000x reference)
#include <cuda_runtime.h>
#include <cstdint>

#define KK 16
#define BB 512
#define NP 4096
#define EPSF 1e-13f
#define TOLF 1.001e-5f   // np.isclose to 1.0: rtol(1e-5)*1.0 + atol(1e-8)

// transposed packed labels, split low/high 8 concepts.
// train point n lives at index (n&7)*512 + (n>>3); beran thread t reads j*512+t.
__device__ uint2 g_lo[NP];   // concepts 0..7, one byte each
__device__ uint2 g_hi[NP];   // concepts 8..15

__global__ void pack_labels_kernel(const int* __restrict__ c_in) {
    int t = blockIdx.x * blockDim.x + threadIdx.x;
    if (t < NP) {
        const int4* p = (const int4*)(c_in + t * KK);
        int4 a = p[0], b = p[1], c = p[2], d = p[3];
        uint2 lo, hi;
        lo.x = (a.x & 255u) | ((a.y & 255u) << 8) | ((a.z & 255u) << 16) | ((a.w & 255u) << 24);
        lo.y = (b.x & 255u) | ((b.y & 255u) << 8) | ((b.z & 255u) << 16) | ((b.w & 255u) << 24);
        hi.x = (c.x & 255u) | ((c.y & 255u) << 8) | ((c.z & 255u) << 16) | ((c.w & 255u) << 24);
        hi.y = (d.x & 255u) | ((d.y & 255u) << 8) | ((d.z & 255u) << 16) | ((d.w & 255u) << 24);
        int idx = (t & 7) * 512 + (t >> 3);
        g_lo[idx] = lo;
        g_hi[idx] = hi;
    }
}

__global__ __launch_bounds__(512, 4) void beran_kernel(
    const float* __restrict__ delta,
    const float* __restrict__ c_p,
    const float* __restrict__ bwp,
    float* __restrict__ out)
{
    __shared__ float s_score[KK * 32];  // 2 KB
    __shared__ float ws1[16];
    __shared__ float ws2[16];
    __shared__ float s_tot_sh, g2_sh;

    const int tid  = threadIdx.x;
    const int lane = tid & 31;
    const int wid  = tid >> 5;          // 0..15
    const int b    = blockIdx.x;
    const unsigned FULL = 0xFFFFFFFFu;

    // ---- Phase A: softmax + score table. warp wid handles concept k=wid ----
    {
        float x = c_p[(wid * BB + b) * 32 + lane];
        float m = x;
        #pragma unroll
        for (int d = 16; d; d >>= 1) m = fmaxf(m, __shfl_xor_sync(FULL, m, d));
        float e = __expf(x - m);
        float s = e;
        #pragma unroll
        for (int d = 16; d; d >>= 1) s += __shfl_xor_sync(FULL, s, d);
        float p = __fdividef(e, s);
        float ssq = p * p;
        #pragma unroll
        for (int d = 16; d; d >>= 1) ssq += __shfl_xor_sync(FULL, ssq, d);
        s_score[wid * 32 + lane] = ssq - 2.0f * p + 1.0f;   // score[k][v]
    }
    __syncthreads();

    const float bw  = fminf(fmaxf(bwp[0], 0.1f), 10.0f);
    const float nib = -1.0f / bw;

    // ---- Phase B: two-pass gather (keeps only 8 sreg live at a time) ----
    float o[8];
    {
        float sreg[8];
        #pragma unroll
        for (int k = 0; k < 8; k++) sreg[k] = s_score[k * 32 + lane];
        #pragma unroll
        for (int j = 0; j < 8; j++) {
            uint2 pk = g_lo[j * 512 + tid];
            float m = 0.0f;
            m += __shfl_sync(FULL, sreg[0], (int)pk.x);
            m += __shfl_sync(FULL, sreg[1], (int)(pk.x >> 8));
            m += __shfl_sync(FULL, sreg[2], (int)(pk.x >> 16));
            m += __shfl_sync(FULL, sreg[3], (int)(pk.x >> 24));
            m += __shfl_sync(FULL, sreg[4], (int)pk.y);
            m += __shfl_sync(FULL, sreg[5], (int)(pk.y >> 8));
            m += __shfl_sync(FULL, sreg[6], (int)(pk.y >> 16));
            m += __shfl_sync(FULL, sreg[7], (int)(pk.y >> 24));
            o[j] = m;
        }
        #pragma unroll
        for (int k = 0; k < 8; k++) sreg[k] = s_score[(k + 8) * 32 + lane];
        #pragma unroll
        for (int j = 0; j < 8; j++) {
            uint2 pk = g_hi[j * 512 + tid];
            float m = o[j];
            m += __shfl_sync(FULL, sreg[0], (int)pk.x);
            m += __shfl_sync(FULL, sreg[1], (int)(pk.x >> 8));
            m += __shfl_sync(FULL, sreg[2], (int)(pk.x >> 16));
            m += __shfl_sync(FULL, sreg[3], (int)(pk.x >> 24));
            m += __shfl_sync(FULL, sreg[4], (int)pk.y);
            m += __shfl_sync(FULL, sreg[5], (int)(pk.y >> 8));
            m += __shfl_sync(FULL, sreg[6], (int)(pk.y >> 16));
            m += __shfl_sync(FULL, sreg[7], (int)(pk.y >> 24));
            o[j] = __expf(m * nib);   // w value
        }
    }

    // ---- Phase C: scan #1 over w; cw built in place over o ----
    #pragma unroll
    for (int j = 1; j < 8; j++) o[j] += o[j - 1];   // o[] is now inclusive cumsum

    float tot = o[7];
    float ti = tot;
    #pragma unroll
    for (int d = 1; d < 32; d <<= 1) {
        float u = __shfl_up_sync(FULL, ti, d);
        if (lane >= d) ti += u;
    }
    if (lane == 31) ws1[wid] = ti;
    __syncthreads();
    if (wid == 0) {
        float v = (lane < 16) ? ws1[lane] : 0.0f;
        float vi = v;
        #pragma unroll
        for (int d = 1; d < 16; d <<= 1) {
            float u = __shfl_up_sync(FULL, vi, d);
            if (lane >= d) vi += u;
        }
        if (lane < 16) ws1[lane] = vi - v;   // exclusive warp-prefix
        if (lane == 15) s_tot_sh = vi;       // grand total s
    }
    __syncthreads();

    const float off1  = ws1[wid] + (ti - tot);
    const float s_tot = s_tot_sh;
    const float tols  = (s_tot < EPSF) ? 3.0e38f : TOLF * s_tot;  // unnormalized guard

    // ---- Phase D: xi = log(t_prev/t); hz built in place over o ----
    float tot2 = 0.0f;
    {
        float tprev = s_tot - off1;
        const float4* dp = (const float4*)(delta + tid * 8);
        #pragma unroll
        for (int jc = 0; jc < 2; jc++) {
            float4 dv = dp[jc];
            #pragma unroll
            for (int l = 0; l < 4; l++) {
                int j = jc * 4 + l;
                float dl = (l == 0) ? dv.x : (l == 1) ? dv.y : (l == 2) ? dv.z : dv.w;
                float t = s_tot - (off1 + o[j]);
                bool bad = (fabsf(t) <= tols) || (fabsf(tprev) <= tols);
                float xi = bad ? 0.0f : __logf(__fdividef(tprev, t));
                float v = dl * xi;
                tot2 += v;
                o[j] = v;            // o[] now holds delta*xi
                tprev = t;
            }
        }
    }
    #pragma unroll
    for (int j = 1; j < 8; j++) o[j] += o[j - 1];   // o[] now local hazard cumsum

    // ---- Phase E: scan #2 (hazards) ----
    float ti2 = tot2;
    #pragma unroll
    for (int d = 1; d < 32; d <<= 1) {
        float u = __shfl_up_sync(FULL, ti2, d);
        if (lane >= d) ti2 += u;
    }
    if (lane == 31) ws2[wid] = ti2;
    __syncthreads();
    if (wid == 0) {
        float v = (lane < 16) ? ws2[lane] : 0.0f;
        float vi = v;
        #pragma unroll
        for (int d = 1; d < 16; d <<= 1) {
            float u = __shfl_up_sync(FULL, vi, d);
            if (lane >= d) vi += u;
        }
        if (lane < 16) ws2[lane] = vi - v;
        if (lane == 15) g2_sh = vi;          // grand total hazards
    }
    __syncthreads();
    const float off2 = ws2[wid] + (ti2 - tot2);

    // s2 telescopes: sum(surv_steps) = 1 - surv[N-1]
    const float s2   = 1.0f - __expf(-g2_sh);
    const float inv2 = (s2 < EPSF) ? 0.0f : 1.0f / s2;
    float prev = (tid == 0) ? 1.0f : __expf(-off2);   // surv[8*tid - 1]

    // ---- Phase F: surv (write), then steps in place ----
    #pragma unroll
    for (int j = 0; j < 8; j++) o[j] = __expf(-(o[j] + off2));   // o[] now surv

    {
        float4* op = (float4*)(out + (size_t)b * NP + tid * 8);
        op[0] = make_float4(o[0], o[1], o[2], o[3]);
        op[1] = make_float4(o[4], o[5], o[6], o[7]);
    }
    #pragma unroll
    for (int j = 0; j < 8; j++) {
        float sj = o[j];
        o[j] = (prev - sj) * inv2;       // o[] now surv_steps
        prev = sj;
    }
    {
        float4* op = (float4*)(out + (size_t)BB * NP + (size_t)b * NP + tid * 8);
        op[0] = make_float4(o[0], o[1], o[2], o[3]);
        op[1] = make_float4(o[4], o[5], o[6], o[7]);
    }
}

extern "C" void kernel_launch(void* const* d_in, const int* in_sizes, int n_in,
                              void* d_out, int out_size) {
    const int*   c_in  = (const int*)d_in[0];
    const float* delta = (const float*)d_in[1];
    const float* c_p   = (const float*)d_in[2];
    const float* bwp   = (const float*)d_in[3];
    float* out = (float*)d_out;

    pack_labels_kernel<<<16, 256>>>(c_in);
    beran_kernel<<<BB, 512>>>(delta, c_p, bwp, out);
}

// round 8
// speedup vs baseline: 1.0122x; 1.0122x over previous
#include <cuda_runtime.h>
#include <cstdint>

#define KK 16
#define BB 512
#define NP 4096
#define EPSF 1e-13f
#define TOLF 1.001e-5f   // np.isclose to 1.0: rtol(1e-5)*1.0 + atol(1e-8)

// transposed packed labels, split low/high 8 concepts.
// train point n lives at index (n&7)*512 + (n>>3); beran thread t reads j*512+t.
__device__ uint2 g_lo[NP];   // concepts 0..7, one byte each
__device__ uint2 g_hi[NP];   // concepts 8..15

__global__ void pack_labels_kernel(const int* __restrict__ c_in) {
    int t = blockIdx.x * blockDim.x + threadIdx.x;
    if (t < NP) {
        const int4* p = (const int4*)(c_in + t * KK);
        int4 a = p[0], b = p[1], c = p[2], d = p[3];
        uint2 lo, hi;
        lo.x = (a.x & 255u) | ((a.y & 255u) << 8) | ((a.z & 255u) << 16) | ((a.w & 255u) << 24);
        lo.y = (b.x & 255u) | ((b.y & 255u) << 8) | ((b.z & 255u) << 16) | ((b.w & 255u) << 24);
        hi.x = (c.x & 255u) | ((c.y & 255u) << 8) | ((c.z & 255u) << 16) | ((c.w & 255u) << 24);
        hi.y = (d.x & 255u) | ((d.y & 255u) << 8) | ((d.z & 255u) << 16) | ((d.w & 255u) << 24);
        int idx = (t & 7) * 512 + (t >> 3);
        g_lo[idx] = lo;
        g_hi[idx] = hi;
    }
}

// Each block processes TWO test samples: b0 = 2*blockIdx, b1 = 2*blockIdx+1.
__global__ __launch_bounds__(512, 2) void beran_kernel(
    const float* __restrict__ delta,
    const float* __restrict__ c_p,
    const float* __restrict__ bwp,
    float* __restrict__ out)
{
    __shared__ float s_score[2 * KK * 32];  // 4 KB: [h][k][v]
    __shared__ float wsA[16], wsB[16];
    __shared__ float stot_sh[2], g2_sh[2];

    const int tid  = threadIdx.x;
    const int lane = tid & 31;
    const int wid  = tid >> 5;          // 0..15
    const int b0   = blockIdx.x * 2;
    const unsigned FULL = 0xFFFFFFFFu;

    // ---- Phase A: softmax + score tables for both samples ----
    #pragma unroll
    for (int h = 0; h < 2; h++) {
        float x = c_p[(wid * BB + b0 + h) * 32 + lane];
        float m = x;
        #pragma unroll
        for (int d = 16; d; d >>= 1) m = fmaxf(m, __shfl_xor_sync(FULL, m, d));
        float e = __expf(x - m);
        float s = e;
        #pragma unroll
        for (int d = 16; d; d >>= 1) s += __shfl_xor_sync(FULL, s, d);
        float p = __fdividef(e, s);
        float ssq = p * p;
        #pragma unroll
        for (int d = 16; d; d >>= 1) ssq += __shfl_xor_sync(FULL, ssq, d);
        s_score[h * 512 + wid * 32 + lane] = ssq - 2.0f * p + 1.0f;
    }
    __syncthreads();

    const float bw  = fminf(fmaxf(bwp[0], 0.1f), 10.0f);
    const float nib = -1.0f / bw;

    // ---- Phase B: two-pass gather, both samples share label loads + shifts ----
    float oa[8], ob[8];
    {
        float srA[8], srB[8];
        #pragma unroll
        for (int k = 0; k < 8; k++) { srA[k] = s_score[k * 32 + lane]; srB[k] = s_score[512 + k * 32 + lane]; }
        #pragma unroll
        for (int j = 0; j < 8; j++) {
            uint2 pk = g_lo[j * 512 + tid];
            int i0 = (int)pk.x, i1 = (int)(pk.x >> 8), i2 = (int)(pk.x >> 16), i3 = (int)(pk.x >> 24);
            int i4 = (int)pk.y, i5 = (int)(pk.y >> 8), i6 = (int)(pk.y >> 16), i7 = (int)(pk.y >> 24);
            float ma = 0.0f, mb = 0.0f;
            ma += __shfl_sync(FULL, srA[0], i0); mb += __shfl_sync(FULL, srB[0], i0);
            ma += __shfl_sync(FULL, srA[1], i1); mb += __shfl_sync(FULL, srB[1], i1);
            ma += __shfl_sync(FULL, srA[2], i2); mb += __shfl_sync(FULL, srB[2], i2);
            ma += __shfl_sync(FULL, srA[3], i3); mb += __shfl_sync(FULL, srB[3], i3);
            ma += __shfl_sync(FULL, srA[4], i4); mb += __shfl_sync(FULL, srB[4], i4);
            ma += __shfl_sync(FULL, srA[5], i5); mb += __shfl_sync(FULL, srB[5], i5);
            ma += __shfl_sync(FULL, srA[6], i6); mb += __shfl_sync(FULL, srB[6], i6);
            ma += __shfl_sync(FULL, srA[7], i7); mb += __shfl_sync(FULL, srB[7], i7);
            oa[j] = ma; ob[j] = mb;
        }
        #pragma unroll
        for (int k = 0; k < 8; k++) { srA[k] = s_score[(k + 8) * 32 + lane]; srB[k] = s_score[512 + (k + 8) * 32 + lane]; }
        #pragma unroll
        for (int j = 0; j < 8; j++) {
            uint2 pk = g_hi[j * 512 + tid];
            int i0 = (int)pk.x, i1 = (int)(pk.x >> 8), i2 = (int)(pk.x >> 16), i3 = (int)(pk.x >> 24);
            int i4 = (int)pk.y, i5 = (int)(pk.y >> 8), i6 = (int)(pk.y >> 16), i7 = (int)(pk.y >> 24);
            float ma = oa[j], mb = ob[j];
            ma += __shfl_sync(FULL, srA[0], i0); mb += __shfl_sync(FULL, srB[0], i0);
            ma += __shfl_sync(FULL, srA[1], i1); mb += __shfl_sync(FULL, srB[1], i1);
            ma += __shfl_sync(FULL, srA[2], i2); mb += __shfl_sync(FULL, srB[2], i2);
            ma += __shfl_sync(FULL, srA[3], i3); mb += __shfl_sync(FULL, srB[3], i3);
            ma += __shfl_sync(FULL, srA[4], i4); mb += __shfl_sync(FULL, srB[4], i4);
            ma += __shfl_sync(FULL, srA[5], i5); mb += __shfl_sync(FULL, srB[5], i5);
            ma += __shfl_sync(FULL, srA[6], i6); mb += __shfl_sync(FULL, srB[6], i6);
            ma += __shfl_sync(FULL, srA[7], i7); mb += __shfl_sync(FULL, srB[7], i7);
            oa[j] = __expf(ma * nib);
            ob[j] = __expf(mb * nib);
        }
    }

    // ---- Phase C: scan #1 (both samples, interleaved) ----
    #pragma unroll
    for (int j = 1; j < 8; j++) { oa[j] += oa[j - 1]; ob[j] += ob[j - 1]; }

    float totA = oa[7], totB = ob[7];
    float tiA = totA, tiB = totB;
    #pragma unroll
    for (int d = 1; d < 32; d <<= 1) {
        float ua = __shfl_up_sync(FULL, tiA, d);
        float ub = __shfl_up_sync(FULL, tiB, d);
        if (lane >= d) { tiA += ua; tiB += ub; }
    }
    if (lane == 31) { wsA[wid] = tiA; wsB[wid] = tiB; }
    __syncthreads();
    if (wid < 2) {   // warp0 scans A partials, warp1 scans B partials
        float* w = (wid == 0) ? wsA : wsB;
        float v = (lane < 16) ? w[lane] : 0.0f;
        float vi = v;
        #pragma unroll
        for (int d = 1; d < 16; d <<= 1) {
            float u = __shfl_up_sync(FULL, vi, d);
            if (lane >= d) vi += u;
        }
        if (lane < 16) w[lane] = vi - v;
        if (lane == 15) stot_sh[wid] = vi;
    }
    __syncthreads();

    const float off1A = wsA[wid] + (tiA - totA);
    const float off1B = wsB[wid] + (tiB - totB);
    const float sA = stot_sh[0], sB = stot_sh[1];
    const float tolA = (sA < EPSF) ? 3.0e38f : TOLF * sA;
    const float tolB = (sB < EPSF) ? 3.0e38f : TOLF * sB;

    // delta shared by both samples
    float dl[8];
    {
        const float4* dp = (const float4*)(delta + tid * 8);
        float4 d0 = dp[0], d1 = dp[1];
        dl[0] = d0.x; dl[1] = d0.y; dl[2] = d0.z; dl[3] = d0.w;
        dl[4] = d1.x; dl[5] = d1.y; dl[6] = d1.z; dl[7] = d1.w;
    }

    // ---- Phase D: xi on unnormalized residuals (both, interleaved) ----
    float tot2A = 0.0f, tot2B = 0.0f;
    {
        float tpA = sA - off1A, tpB = sB - off1B;
        #pragma unroll
        for (int j = 0; j < 8; j++) {
            float tA = sA - (off1A + oa[j]);
            float tB = sB - (off1B + ob[j]);
            bool badA = (fabsf(tA) <= tolA) || (fabsf(tpA) <= tolA);
            bool badB = (fabsf(tB) <= tolB) || (fabsf(tpB) <= tolB);
            float xiA = badA ? 0.0f : __logf(__fdividef(tpA, tA));
            float xiB = badB ? 0.0f : __logf(__fdividef(tpB, tB));
            float vA = dl[j] * xiA, vB = dl[j] * xiB;
            tot2A += vA; tot2B += vB;
            oa[j] = vA; ob[j] = vB;
            tpA = tA; tpB = tB;
        }
    }
    #pragma unroll
    for (int j = 1; j < 8; j++) { oa[j] += oa[j - 1]; ob[j] += ob[j - 1]; }

    // ---- Phase E: scan #2 (both) ----
    float ti2A = tot2A, ti2B = tot2B;
    #pragma unroll
    for (int d = 1; d < 32; d <<= 1) {
        float ua = __shfl_up_sync(FULL, ti2A, d);
        float ub = __shfl_up_sync(FULL, ti2B, d);
        if (lane >= d) { ti2A += ua; ti2B += ub; }
    }
    __syncthreads();   // off1 reads complete before ws reuse
    if (lane == 31) { wsA[wid] = ti2A; wsB[wid] = ti2B; }
    __syncthreads();
    if (wid < 2) {
        float* w = (wid == 0) ? wsA : wsB;
        float v = (lane < 16) ? w[lane] : 0.0f;
        float vi = v;
        #pragma unroll
        for (int d = 1; d < 16; d <<= 1) {
            float u = __shfl_up_sync(FULL, vi, d);
            if (lane >= d) vi += u;
        }
        if (lane < 16) w[lane] = vi - v;
        if (lane == 15) g2_sh[wid] = vi;
    }
    __syncthreads();
    const float off2A = wsA[wid] + (ti2A - tot2A);
    const float off2B = wsB[wid] + (ti2B - tot2B);

    const float s2A = 1.0f - __expf(-g2_sh[0]);
    const float s2B = 1.0f - __expf(-g2_sh[1]);
    const float inv2A = (s2A < EPSF) ? 0.0f : 1.0f / s2A;
    const float inv2B = (s2B < EPSF) ? 0.0f : 1.0f / s2B;
    float prevA = (tid == 0) ? 1.0f : __expf(-off2A);
    float prevB = (tid == 0) ? 1.0f : __expf(-off2B);

    // ---- Phase F: surv + steps, both samples ----
    #pragma unroll
    for (int j = 0; j < 8; j++) {
        oa[j] = __expf(-(oa[j] + off2A));
        ob[j] = __expf(-(ob[j] + off2B));
    }
    {
        float4* opA = (float4*)(out + (size_t)b0 * NP + tid * 8);
        float4* opB = (float4*)(out + (size_t)(b0 + 1) * NP + tid * 8);
        opA[0] = make_float4(oa[0], oa[1], oa[2], oa[3]);
        opA[1] = make_float4(oa[4], oa[5], oa[6], oa[7]);
        opB[0] = make_float4(ob[0], ob[1], ob[2], ob[3]);
        opB[1] = make_float4(ob[4], ob[5], ob[6], ob[7]);
    }
    #pragma unroll
    for (int j = 0; j < 8; j++) {
        float sa = oa[j], sb = ob[j];
        oa[j] = (prevA - sa) * inv2A;
        ob[j] = (prevB - sb) * inv2B;
        prevA = sa; prevB = sb;
    }
    {
        float4* opA = (float4*)(out + (size_t)BB * NP + (size_t)b0 * NP + tid * 8);
        float4* opB = (float4*)(out + (size_t)BB * NP + (size_t)(b0 + 1) * NP + tid * 8);
        opA[0] = make_float4(oa[0], oa[1], oa[2], oa[3]);
        opA[1] = make_float4(oa[4], oa[5], oa[6], oa[7]);
        opB[0] = make_float4(ob[0], ob[1], ob[2], ob[3]);
        opB[1] = make_float4(ob[4], ob[5], ob[6], ob[7]);
    }
}

extern "C" void kernel_launch(void* const* d_in, const int* in_sizes, int n_in,
                              void* d_out, int out_size) {
    const int*   c_in  = (const int*)d_in[0];
    const float* delta = (const float*)d_in[1];
    const float* c_p   = (const float*)d_in[2];
    const float* bwp   = (const float*)d_in[3];
    float* out = (float*)d_out;

    pack_labels_kernel<<<16, 256>>>(c_in);
    beran_kernel<<<BB / 2, 512>>>(delta, c_p, bwp, out);
}

// round 9
// speedup vs baseline: 1.1394x; 1.1256x over previous
#include <cuda_runtime.h>
#include <cstdint>

#define KK 16
#define BB 512
#define NP 4096
#define EPSF 1e-13f
#define TOLF 1.001e-5f       // np.isclose to 1.0: rtol(1e-5)*1.0 + atol(1e-8)
#define LOG2E 1.4426950408889634f

// labels split into 4 planes; plane p holds concepts 4p..4p+3 (one byte each).
// train point n lives at plane index (n&3)*1024 + (n>>2);
// beran thread t (owning n = 4t..4t+3) reads g_pk[p][j*1024 + t] -> coalesced.
__device__ unsigned g_pk[4][NP];

__global__ void pack_labels_kernel(const int* __restrict__ c_in) {
    int t = blockIdx.x * blockDim.x + threadIdx.x;
    if (t < NP) {
        const int4* p = (const int4*)(c_in + t * KK);
        int idx = (t & 3) * 1024 + (t >> 2);
        #pragma unroll
        for (int q = 0; q < 4; q++) {
            int4 a = p[q];
            g_pk[q][idx] = (a.x & 255u) | ((a.y & 255u) << 8)
                         | ((a.z & 255u) << 16) | ((a.w & 255u) << 24);
        }
    }
}

// Each block: 1024 threads, TWO samples (b0, b0+1), 4 train points per thread.
__global__ __launch_bounds__(1024, 2) void beran_kernel(
    const float* __restrict__ delta,
    const float* __restrict__ c_p,
    const float* __restrict__ bwp,
    float* __restrict__ out)
{
    __shared__ float s_score[2 * KK * 32];  // 4 KB: [h][k][v]
    __shared__ float wsA[32], wsB[32];
    __shared__ float stot_sh[2], g2_sh[2];

    const int tid  = threadIdx.x;
    const int lane = tid & 31;
    const int wid  = tid >> 5;          // 0..31
    const int b0   = blockIdx.x * 2;
    const unsigned FULL = 0xFFFFFFFFu;

    // ---- Phase A: 32 softmax tasks, one per warp: h = wid>>4, k = wid&15 ----
    {
        int h = wid >> 4, k = wid & 15;
        float x = c_p[(k * BB + b0 + h) * 32 + lane];
        float m = x;
        #pragma unroll
        for (int d = 16; d; d >>= 1) m = fmaxf(m, __shfl_xor_sync(FULL, m, d));
        float e = __expf(x - m);
        float s = e;
        #pragma unroll
        for (int d = 16; d; d >>= 1) s += __shfl_xor_sync(FULL, s, d);
        float p = __fdividef(e, s);
        float ssq = p * p;
        #pragma unroll
        for (int d = 16; d; d >>= 1) ssq += __shfl_xor_sync(FULL, ssq, d);
        s_score[h * 512 + k * 32 + lane] = ssq - 2.0f * p + 1.0f;
    }
    __syncthreads();

    const float bw   = fminf(fmaxf(bwp[0], 0.1f), 10.0f);
    const float nib2 = -LOG2E / bw;     // base-2 exponent scale

    // ---- Phase B: gather in 4 quarter-passes (4 concepts at a time) ----
    float oa[4] = {0, 0, 0, 0}, ob[4] = {0, 0, 0, 0};
    #pragma unroll
    for (int q = 0; q < 4; q++) {
        float srA[4], srB[4];
        #pragma unroll
        for (int kk = 0; kk < 4; kk++) {
            srA[kk] = s_score[(q * 4 + kk) * 32 + lane];
            srB[kk] = s_score[512 + (q * 4 + kk) * 32 + lane];
        }
        #pragma unroll
        for (int j = 0; j < 4; j++) {
            unsigned pk = g_pk[q][j * 1024 + tid];
            int i0 = (int)pk, i1 = (int)(pk >> 8), i2 = (int)(pk >> 16), i3 = (int)(pk >> 24);
            float ma = oa[j], mb = ob[j];
            ma += __shfl_sync(FULL, srA[0], i0); mb += __shfl_sync(FULL, srB[0], i0);
            ma += __shfl_sync(FULL, srA[1], i1); mb += __shfl_sync(FULL, srB[1], i1);
            ma += __shfl_sync(FULL, srA[2], i2); mb += __shfl_sync(FULL, srB[2], i2);
            ma += __shfl_sync(FULL, srA[3], i3); mb += __shfl_sync(FULL, srB[3], i3);
            oa[j] = ma; ob[j] = mb;
        }
    }
    // w values
    #pragma unroll
    for (int j = 0; j < 4; j++) {
        oa[j] = exp2f(oa[j] * nib2);
        ob[j] = exp2f(ob[j] * nib2);
    }

    // ---- Phase C: scan #1 (cumsum of w), in place ----
    #pragma unroll
    for (int j = 1; j < 4; j++) { oa[j] += oa[j - 1]; ob[j] += ob[j - 1]; }

    float totA = oa[3], totB = ob[3];
    float tiA = totA, tiB = totB;
    #pragma unroll
    for (int d = 1; d < 32; d <<= 1) {
        float ua = __shfl_up_sync(FULL, tiA, d);
        float ub = __shfl_up_sync(FULL, tiB, d);
        if (lane >= d) { tiA += ua; tiB += ub; }
    }
    if (lane == 31) { wsA[wid] = tiA; wsB[wid] = tiB; }
    __syncthreads();
    if (wid < 2) {   // warp0: A partials (32 of them); warp1: B
        float* w = (wid == 0) ? wsA : wsB;
        float v = w[lane];
        float vi = v;
        #pragma unroll
        for (int d = 1; d < 32; d <<= 1) {
            float u = __shfl_up_sync(FULL, vi, d);
            if (lane >= d) vi += u;
        }
        w[lane] = vi - v;                 // exclusive warp prefix
        if (lane == 31) stot_sh[wid] = vi; // grand total
    }
    __syncthreads();

    const float off1A = wsA[wid] + (tiA - totA);
    const float off1B = wsB[wid] + (tiB - totB);
    const float sA = stot_sh[0], sB = stot_sh[1];
    const float tolA = (sA < EPSF) ? 3.0e38f : TOLF * sA;
    const float tolB = (sB < EPSF) ? 3.0e38f : TOLF * sB;

    // ---- Phase D: xi = log2(t_prev/t) on unnormalized residuals ----
    float tot2A = 0.0f, tot2B = 0.0f;
    {
        float4 dv = ((const float4*)(delta))[tid];   // delta[4t..4t+3]
        float tpA = sA - off1A, tpB = sB - off1B;
        #pragma unroll
        for (int j = 0; j < 4; j++) {
            float dl = (j == 0) ? dv.x : (j == 1) ? dv.y : (j == 2) ? dv.z : dv.w;
            float tA = sA - (off1A + oa[j]);
            float tB = sB - (off1B + ob[j]);
            bool badA = (fabsf(tA) <= tolA) || (fabsf(tpA) <= tolA);
            bool badB = (fabsf(tB) <= tolB) || (fabsf(tpB) <= tolB);
            float xiA = badA ? 0.0f : __log2f(__fdividef(tpA, tA));
            float xiB = badB ? 0.0f : __log2f(__fdividef(tpB, tB));
            float vA = dl * xiA, vB = dl * xiB;
            tot2A += vA; tot2B += vB;
            oa[j] = vA; ob[j] = vB;       // o[] now delta*xi (log2 units)
            tpA = tA; tpB = tB;
        }
    }
    #pragma unroll
    for (int j = 1; j < 4; j++) { oa[j] += oa[j - 1]; ob[j] += ob[j - 1]; }

    // ---- Phase E: scan #2 (hazards, log2 units) ----
    float ti2A = tot2A, ti2B = tot2B;
    #pragma unroll
    for (int d = 1; d < 32; d <<= 1) {
        float ua = __shfl_up_sync(FULL, ti2A, d);
        float ub = __shfl_up_sync(FULL, ti2B, d);
        if (lane >= d) { ti2A += ua; ti2B += ub; }
    }
    __syncthreads();   // off1 reads complete before ws reuse
    if (lane == 31) { wsA[wid] = ti2A; wsB[wid] = ti2B; }
    __syncthreads();
    if (wid < 2) {
        float* w = (wid == 0) ? wsA : wsB;
        float v = w[lane];
        float vi = v;
        #pragma unroll
        for (int d = 1; d < 32; d <<= 1) {
            float u = __shfl_up_sync(FULL, vi, d);
            if (lane >= d) vi += u;
        }
        w[lane] = vi - v;
        if (lane == 31) g2_sh[wid] = vi;
    }
    __syncthreads();
    const float off2A = wsA[wid] + (ti2A - tot2A);
    const float off2B = wsB[wid] + (ti2B - tot2B);

    // s2 telescopes: sum(surv_steps) = 1 - surv[N-1] ; surv = exp2(-hz2)
    const float s2A = 1.0f - exp2f(-g2_sh[0]);
    const float s2B = 1.0f - exp2f(-g2_sh[1]);
    const float inv2A = (s2A < EPSF) ? 0.0f : 1.0f / s2A;
    const float inv2B = (s2B < EPSF) ? 0.0f : 1.0f / s2B;
    float prevA = (tid == 0) ? 1.0f : exp2f(-off2A);
    float prevB = (tid == 0) ? 1.0f : exp2f(-off2B);

    // ---- Phase F: surv (write), then steps in place ----
    #pragma unroll
    for (int j = 0; j < 4; j++) {
        oa[j] = exp2f(-(oa[j] + off2A));
        ob[j] = exp2f(-(ob[j] + off2B));
    }
    {
        float4* opA = (float4*)(out + (size_t)b0 * NP) + tid;
        float4* opB = (float4*)(out + (size_t)(b0 + 1) * NP) + tid;
        opA[0] = make_float4(oa[0], oa[1], oa[2], oa[3]);
        opB[0] = make_float4(ob[0], ob[1], ob[2], ob[3]);
    }
    #pragma unroll
    for (int j = 0; j < 4; j++) {
        float sa = oa[j], sb = ob[j];
        oa[j] = (prevA - sa) * inv2A;
        ob[j] = (prevB - sb) * inv2B;
        prevA = sa; prevB = sb;
    }
    {
        float4* opA = (float4*)(out + (size_t)BB * NP + (size_t)b0 * NP) + tid;
        float4* opB = (float4*)(out + (size_t)BB * NP + (size_t)(b0 + 1) * NP) + tid;
        opA[0] = make_float4(oa[0], oa[1], oa[2], oa[3]);
        opB[0] = make_float4(ob[0], ob[1], ob[2], ob[3]);
    }
}

extern "C" void kernel_launch(void* const* d_in, const int* in_sizes, int n_in,
                              void* d_out, int out_size) {
    const int*   c_in  = (const int*)d_in[0];
    const float* delta = (const float*)d_in[1];
    const float* c_p   = (const float*)d_in[2];
    const float* bwp   = (const float*)d_in[3];
    float* out = (float*)d_out;

    pack_labels_kernel<<<32, 128>>>(c_in);
    beran_kernel<<<BB / 2, 1024>>>(delta, c_p, bwp, out);
}